// round 1
// baseline (speedup 1.0000x reference)
#include <cuda_runtime.h>
#include <math.h>

// ---------------- scratch (static __device__, no allocs) ----------------
__device__ unsigned int g_adj[128 * 4];      // adjacency bitmask: row d, bit s
__device__ float g_P[128 * 512];
__device__ float g_Q[128 * 512];
__device__ float g_h1[128 * 512];
__device__ float g_h2[128 * 512];
__device__ float g_partial[128 * 512];
__device__ float g_v0[512];

// ---------------- adjacency ----------------
__global__ void zero_adj_kernel() {
    g_adj[threadIdx.x] = 0u;   // 512 threads
}

__global__ void build_adj_kernel(const int* __restrict__ ei, int E) {
    __shared__ unsigned int s_adj[512];
    for (int i = threadIdx.x; i < 512; i += blockDim.x) s_adj[i] = 0u;
    __syncthreads();
    int stride = gridDim.x * blockDim.x;
    for (int e = blockIdx.x * blockDim.x + threadIdx.x; e < E; e += stride) {
        int s = ei[e];        // src
        int d = ei[E + e];    // dst
        atomicOr(&s_adj[(d << 2) + (s >> 5)], 1u << (s & 31));
    }
    __syncthreads();
    for (int i = threadIdx.x; i < 512; i += blockDim.x) {
        unsigned int w = s_adj[i];
        if (w) atomicOr(&g_adj[i], w);
    }
}

// ---------------- P/Q mini-GEMMs ----------------
// P[d,h] = b1[h] + sum_k x[d,k]*(W1[k,h] - W1[C+k,h])
// Q[d,h] =         sum_k x[d,k]*W1[C+k,h]
// grid = 128 (d), block = 512 (h)
__global__ void pq_kernel(const float* __restrict__ x_ext,
                          const float* __restrict__ W1,
                          const float* __restrict__ b1,
                          int C, int use_h1) {
    __shared__ float xs[512];
    const float* xin = use_h1 ? g_h1 : x_ext;
    int d = blockIdx.x, h = threadIdx.x;
    if (h < C) xs[h] = xin[d * C + h];
    __syncthreads();
    float p = b1[h], q = 0.f;
    for (int k = 0; k < C; k++) {
        float xv = xs[k];
        float wt = W1[k * 512 + h];
        float wb = W1[(C + k) * 512 + h];
        p = fmaf(xv, wt - wb, p);
        q = fmaf(xv, wb, q);
    }
    g_P[d * 512 + h] = p;
    g_Q[d * 512 + h] = q;
}

// ---------------- fused pair-GEMM + masked segment-max ----------------
// For block (nb, d): out[d, nb..nb+63] = relu( max_{s in adj[d]} ( relu(P[d,:]+Q[s,:]) @ W2[:, nb..] ) + b2 )
// BM = 128 (all s), BN = 64, BK = 16, 256 threads, 8x4 micro-tile.
#define BK 16
#define ASTRIDE 132
#define BSTRIDE 68

__global__ __launch_bounds__(256) void gemm_max_kernel(
    const float* __restrict__ W2, const float* __restrict__ b2, int outSel)
{
    __shared__ float Pds[512];
    __shared__ float As[BK * ASTRIDE];
    __shared__ float Bs[BK * BSTRIDE];
    __shared__ unsigned int uadj[4];

    int t = threadIdx.x;
    int d = blockIdx.y;
    int nb = blockIdx.x * 64;
    int ty = t >> 4, tx = t & 15;

    Pds[t]       = g_P[d * 512 + t];
    Pds[t + 256] = g_P[d * 512 + t + 256];
    if (t < 4) uadj[t] = g_adj[(d << 2) + t];

    float acc[8][4];
    #pragma unroll
    for (int r = 0; r < 8; r++)
        #pragma unroll
        for (int c = 0; c < 4; c++) acc[r][c] = 0.f;

    for (int k0 = 0; k0 < 512; k0 += BK) {
        __syncthreads();
        #pragma unroll
        for (int i = 0; i < 8; i++) {
            int idx = i * 256 + t;
            int kk = idx & 15, s = idx >> 4;
            As[kk * ASTRIDE + s] = fmaxf(Pds[k0 + kk] + g_Q[s * 512 + k0 + kk], 0.f);
        }
        #pragma unroll
        for (int i = 0; i < 4; i++) {
            int idx = i * 256 + t;
            int n = idx & 63, kk = idx >> 6;
            Bs[kk * BSTRIDE + n] = W2[(k0 + kk) * 512 + nb + n];
        }
        __syncthreads();
        #pragma unroll
        for (int kk = 0; kk < BK; kk++) {
            float a[8], b[4];
            #pragma unroll
            for (int r = 0; r < 8; r++) a[r] = As[kk * ASTRIDE + ty * 8 + r];
            #pragma unroll
            for (int c = 0; c < 4; c++) b[c] = Bs[kk * BSTRIDE + tx * 4 + c];
            #pragma unroll
            for (int r = 0; r < 8; r++)
                #pragma unroll
                for (int c = 0; c < 4; c++) acc[r][c] = fmaf(a[r], b[c], acc[r][c]);
        }
    }

    // masked max over this thread's 8 s-rows
    float cm[4] = {-INFINITY, -INFINITY, -INFINITY, -INFINITY};
    #pragma unroll
    for (int r = 0; r < 8; r++) {
        int s = ty * 8 + r;
        if ((uadj[s >> 5] >> (s & 31)) & 1u) {
            #pragma unroll
            for (int c = 0; c < 4; c++) cm[c] = fmaxf(cm[c], acc[r][c]);
        }
    }
    __syncthreads();   // Bs reuse as reduction buffer
    #pragma unroll
    for (int c = 0; c < 4; c++) Bs[ty * BSTRIDE + tx * 4 + c] = cm[c];
    __syncthreads();
    if (t < 64) {
        float m = -INFINITY;
        #pragma unroll
        for (int r = 0; r < 16; r++) m = fmaxf(m, Bs[r * BSTRIDE + t]);
        float* outp = outSel ? g_h2 : g_h1;
        // empty segment -> -inf -> where(finite,.,0)=0; outer relu => fmaxf(.,0)
        outp[d * 512 + nb + t] = fmaxf(m + b2[nb + t], 0.f);
    }
}

// ---------------- dense head ----------------
// v[65536] = flatten(h2); split-K GEMV: block kb handles k in [kb*512, kb*512+512)
__global__ void dense_partial_kernel(const float* __restrict__ linW) {
    __shared__ float vs[512];
    int kb = blockIdx.x, t = threadIdx.x;   // 512 threads
    vs[t] = g_h2[kb * 512 + t];
    __syncthreads();
    float acc = 0.f;
    const float* W = linW + (size_t)kb * 512 * 512;
    #pragma unroll 4
    for (int k = 0; k < 512; k++)
        acc = fmaf(vs[k], W[(size_t)k * 512 + t], acc);
    g_partial[kb * 512 + t] = acc;
}

__global__ void dense_reduce_kernel(const float* __restrict__ lin_b) {
    int t = threadIdx.x;   // 512
    float s = 0.f;
    #pragma unroll 8
    for (int b = 0; b < 128; b++) s += g_partial[b * 512 + t];
    g_v0[t] = fmaxf(s + lin_b[t], 0.f);
}

// lin1 (512->256) + out (256->128) + relu + softmax, single block of 256
__global__ void head_kernel(const float* __restrict__ lin1W, const float* __restrict__ lin1b,
                            const float* __restrict__ outW, const float* __restrict__ outb,
                            float* __restrict__ out) {
    __shared__ float v0s[512];
    __shared__ float v1s[256];
    __shared__ float lg[128];
    __shared__ float es[128];
    int t = threadIdx.x;   // 256
    v0s[t]       = g_v0[t];
    v0s[t + 256] = g_v0[t + 256];
    __syncthreads();
    float a = lin1b[t];
    for (int k = 0; k < 512; k++) a = fmaf(v0s[k], lin1W[k * 256 + t], a);
    v1s[t] = fmaxf(a, 0.f);
    __syncthreads();
    if (t < 128) {
        float a2 = outb[t];
        for (int k = 0; k < 256; k++) a2 = fmaf(v1s[k], outW[k * 128 + t], a2);
        lg[t] = fmaxf(a2, 0.f);
    }
    __syncthreads();
    if (t < 128) {
        float mx = -INFINITY;
        for (int i = 0; i < 128; i++) mx = fmaxf(mx, lg[i]);
        es[t] = expf(lg[t] - mx);
    }
    __syncthreads();
    if (t < 128) {
        float sm = 0.f;
        for (int i = 0; i < 128; i++) sm += es[i];
        out[t] = es[t] / sm;
    }
}

// ---------------- launch ----------------
extern "C" void kernel_launch(void* const* d_in, const int* in_sizes, int n_in,
                              void* d_out, int out_size) {
    const float* x     = (const float*)d_in[0];
    const int*   ei    = (const int*)d_in[1];
    const float* c1W1  = (const float*)d_in[2];
    const float* c1b1  = (const float*)d_in[3];
    const float* c1W2  = (const float*)d_in[4];
    const float* c1b2  = (const float*)d_in[5];
    const float* c2W1  = (const float*)d_in[6];
    const float* c2b1  = (const float*)d_in[7];
    const float* c2W2  = (const float*)d_in[8];
    const float* c2b2  = (const float*)d_in[9];
    const float* linW  = (const float*)d_in[10];
    const float* linb  = (const float*)d_in[11];
    const float* lin1W = (const float*)d_in[12];
    const float* lin1b = (const float*)d_in[13];
    const float* outW  = (const float*)d_in[14];
    const float* outb  = (const float*)d_in[15];
    float* out = (float*)d_out;
    int E = in_sizes[1] / 2;

    zero_adj_kernel<<<1, 512>>>();
    build_adj_kernel<<<128, 256>>>(ei, E);

    // EdgeConv 1 (C = 256)
    pq_kernel<<<128, 512>>>(x, c1W1, c1b1, 256, 0);
    gemm_max_kernel<<<dim3(8, 128), 256>>>(c1W2, c1b2, 0);

    // EdgeConv 2 (C = 512)
    pq_kernel<<<128, 512>>>(nullptr, c2W1, c2b1, 512, 1);
    gemm_max_kernel<<<dim3(8, 128), 256>>>(c2W2, c2b2, 1);

    // dense head
    dense_partial_kernel<<<128, 512>>>(linW);
    dense_reduce_kernel<<<1, 512>>>(linb);
    head_kernel<<<1, 256>>>(lin1W, lin1b, outW, outb, out);
}